// round 7
// baseline (speedup 1.0000x reference)
#include <cuda_runtime.h>
#include <cstdint>

// CAModel: y = [x, sobel_x(x), sobel_y(x)] (48 feats) -> relu(y@w0^T+b0) (128)
//          -> @w1^T (16) -> x + update*mask
// Shapes: x[4,16,512,512] f32, w0[128,48], b0[128], w1[16,128], rand_u[4,1,512,512]
//
// Block = 128 contiguous pixels of one image row. GEMMs use packed fp32x2 FMA
// (sm_103a FFMA2 via PTX fma.rn.f32x2) — exact fp32, 2x fma-pipe throughput.

#define PITCH 132          // float pitch for [.. ][128] tiles (16B-aligned rows)
#define YS_OFF   0                       // ys  [48][PITCH]
#define W0_OFF   (48 * PITCH)            // w0s [48][PITCH] (128 cols used), w0s[k][o]
#define W1_OFF   (W0_OFF + 48 * PITCH)   // w1s [128][16],  w1s[o][ko]
#define B0_OFF   (W1_OFF + 128 * 16)     // b0s [128]
#define U_OFF    (B0_OFF + 128)          // union: halo [16][3][PITCH] (6336) / Hs [64][PITCH] (8448)
#define SMEM_FLOATS (U_OFF + 64 * PITCH)
#define SMEM_BYTES  (SMEM_FLOATS * 4)

// ---- packed fp32x2 helpers (sm_103a) ----
typedef unsigned long long u64;

__device__ __forceinline__ u64 pack2(float lo, float hi) {
    u64 r;
    asm("mov.b64 %0, {%1, %2};" : "=l"(r) : "r"(__float_as_uint(lo)), "r"(__float_as_uint(hi)));
    return r;
}
__device__ __forceinline__ void unpack2(u64 v, float& lo, float& hi) {
    uint32_t a, b;
    asm("mov.b64 {%0, %1}, %2;" : "=r"(a), "=r"(b) : "l"(v));
    lo = __uint_as_float(a); hi = __uint_as_float(b);
}
__device__ __forceinline__ u64 fma2(u64 a, u64 b, u64 c) {
    u64 r;
    asm("fma.rn.f32x2 %0, %1, %2, %3;" : "=l"(r) : "l"(a), "l"(b), "l"(c));
    return r;
}
__device__ __forceinline__ u64 add2(u64 a, u64 b) {
    u64 r;
    asm("add.rn.f32x2 %0, %1, %2;" : "=l"(r) : "l"(a), "l"(b));
    return r;
}

__global__ void __launch_bounds__(256, 2)
ca_kernel(const float* __restrict__ x, const float* __restrict__ w0,
          const float* __restrict__ b0, const float* __restrict__ w1,
          const float* __restrict__ ru, float* __restrict__ out)
{
    extern __shared__ float sm[];
    float* ys  = sm + YS_OFF;
    float* w0s = sm + W0_OFF;
    float* w1s = sm + W1_OFF;
    float* b0s = sm + B0_OFF;
    float* us  = sm + U_OFF;   // halo, then H chunk, then reduction buffer

    const int tid    = threadIdx.x;
    const int colblk = blockIdx.x;   // 0..3
    const int row    = blockIdx.y;   // 0..511
    const int b      = blockIdx.z;   // 0..3
    const int col0   = colblk * 128;

    // ---------- halo load: us[ch][r][j], j=0..129 maps to gcol = col0 + j - 1 ----------
    {
        const long xbase = (long)b * 16 * 512 * 512;
        for (int idx = tid; idx < 16 * 3 * PITCH; idx += 256) {
            int col = idx % PITCH;
            int t   = idx / PITCH;
            int r   = t % 3;
            int ch  = t / 3;
            int gcol = col0 + col - 1;
            int grow = row + r - 1;
            float v = 0.0f;
            if (gcol >= 0 && gcol < 512 && grow >= 0 && grow < 512)
                v = x[xbase + ((long)ch * 512 + grow) * 512 + gcol];
            us[idx] = v;
        }
    }
    __syncthreads();

    // ---------- feature build ys[48][PITCH]: rows 0..15 x, 16..31 gx, 32..47 gy ----------
    for (int idx = tid; idx < 16 * 128; idx += 256) {
        int p  = idx & 127;
        int ch = idx >> 7;
        const float* h0 = us + (ch * 3 + 0) * PITCH + p; // x[row-1][p-1 ..]
        const float* h1 = us + (ch * 3 + 1) * PITCH + p;
        const float* h2 = us + (ch * 3 + 2) * PITCH + p;
        float a00 = h0[0], a01 = h0[1], a02 = h0[2];
        float a10 = h1[0],              a12 = h1[2];
        float a20 = h2[0], a21 = h2[1], a22 = h2[2];
        // cross-correlation with sobel kernels (XLA conv does not flip)
        float gx = (a02 - a00) + 2.0f * (a12 - a10) + (a22 - a20);
        float gy = (a20 + 2.0f * a21 + a22) - (a00 + 2.0f * a01 + a02);
        ys[ch * PITCH + p]        = h1[1]; // center x
        ys[(16 + ch) * PITCH + p] = gx;
        ys[(32 + ch) * PITCH + p] = gy;
    }
    // weights (transposed into smem)
    for (int idx = tid; idx < 128 * 48; idx += 256) {
        int k = idx % 48, o = idx / 48;       // coalesced read of w0[o][k]
        w0s[k * PITCH + o] = w0[idx];
    }
    for (int idx = tid; idx < 16 * 128; idx += 256) {
        int o = idx & 127, ko = idx >> 7;     // coalesced read of w1[ko][o]
        w1s[o * 16 + ko] = w1[idx];
    }
    if (tid < 128) b0s[tid] = b0[tid];
    __syncthreads();

    // ---------- GEMM mappings ----------
    const int pg  = tid >> 4;        // 0..15 : 8 pixels each (GEMM1)
    const int og  = tid & 15;        // 0..15 : 4 hidden each (GEMM1)
    const int pg8 = pg * 8;

    const int g2_os  = tid >> 7;          // 0..1 : hidden split (GEMM2)
    const int g2_kog = (tid >> 5) & 3;    // 0..3 : 4 out-ch each
    const int g2_pg  = tid & 31;          // 0..31: 4 pixels each

    // GEMM2 accumulators: u2[pp][i] = packed {pix 2pp, pix 2pp+1} for out-ch i
    u64 u2[2][4];
#pragma unroll
    for (int pp = 0; pp < 2; ++pp)
#pragma unroll
        for (int i = 0; i < 4; ++i) u2[pp][i] = 0ull;

#pragma unroll
    for (int c = 0; c < 2; ++c) {
        const int cb = c * 64;

        // ----- GEMM1: H[p][o] = relu(b0[o] + sum_k y[k][p] * w0s[k][o]) -----
        // acc2[pp][i] = packed {pix 2pp, pix 2pp+1} for hidden (cb + og*4 + i)
        u64 acc2[4][4];
        {
            float4 bv = *(const float4*)&b0s[cb + og * 4];
            u64 bp[4] = {pack2(bv.x, bv.x), pack2(bv.y, bv.y),
                         pack2(bv.z, bv.z), pack2(bv.w, bv.w)};
#pragma unroll
            for (int pp = 0; pp < 4; ++pp)
#pragma unroll
                for (int i = 0; i < 4; ++i) acc2[pp][i] = bp[i];
        }
#pragma unroll 4
        for (int k = 0; k < 48; ++k) {
            // 8 pixels arrive pre-packed as 4 f32x2 pairs (16B-aligned loads)
            const ulonglong2* yp = (const ulonglong2*)&ys[k * PITCH + pg8];
            ulonglong2 ya = yp[0];
            ulonglong2 yb = yp[1];
            u64 yq[4] = {ya.x, ya.y, yb.x, yb.y};
            float4 wv = *(const float4*)&w0s[k * PITCH + cb + og * 4];
            u64 wq[4] = {pack2(wv.x, wv.x), pack2(wv.y, wv.y),
                         pack2(wv.z, wv.z), pack2(wv.w, wv.w)};
#pragma unroll
            for (int pp = 0; pp < 4; ++pp)
#pragma unroll
                for (int i = 0; i < 4; ++i)
                    acc2[pp][i] = fma2(yq[pp], wq[i], acc2[pp][i]);
        }
        // relu + store H chunk as Hs[o_local][p]
#pragma unroll
        for (int i = 0; i < 4; ++i) {
            float p0,p1,p2,p3,p4,p5,p6,p7;
            unpack2(acc2[0][i], p0, p1);
            unpack2(acc2[1][i], p2, p3);
            unpack2(acc2[2][i], p4, p5);
            unpack2(acc2[3][i], p6, p7);
            float4 v0, v1;
            v0.x = fmaxf(p0, 0.0f); v0.y = fmaxf(p1, 0.0f);
            v0.z = fmaxf(p2, 0.0f); v0.w = fmaxf(p3, 0.0f);
            v1.x = fmaxf(p4, 0.0f); v1.y = fmaxf(p5, 0.0f);
            v1.z = fmaxf(p6, 0.0f); v1.w = fmaxf(p7, 0.0f);
            *(float4*)&us[(og * 4 + i) * PITCH + pg8]     = v0;
            *(float4*)&us[(og * 4 + i) * PITCH + pg8 + 4] = v1;
        }
        __syncthreads();

        // ----- GEMM2 partial: u[p][ko] += H[o][p] * w1s[o][ko] over half the chunk -----
#pragma unroll 4
        for (int j = 0; j < 32; ++j) {
            int ol = g2_os * 32 + j;
            // 4 pixels arrive pre-packed as 2 f32x2 pairs (16B-aligned)
            ulonglong2 hv = *(const ulonglong2*)&us[ol * PITCH + g2_pg * 4];
            float4 wv = *(const float4*)&w1s[(cb + ol) * 16 + g2_kog * 4];
            u64 wq[4] = {pack2(wv.x, wv.x), pack2(wv.y, wv.y),
                         pack2(wv.z, wv.z), pack2(wv.w, wv.w)};
#pragma unroll
            for (int i = 0; i < 4; ++i) {
                u2[0][i] = fma2(hv.x, wq[i], u2[0][i]);
                u2[1][i] = fma2(hv.y, wq[i], u2[1][i]);
            }
        }
        __syncthreads();   // protects Hs reuse next chunk / reduction buffer below
    }

    // ---------- reduce the 2-way hidden split through smem (packed) ----------
    if (g2_os == 1) {
        u64* rp = (u64*)(us + (tid - 128) * 16);
#pragma unroll
        for (int pp = 0; pp < 2; ++pp)
#pragma unroll
            for (int i = 0; i < 4; ++i)
                rp[pp * 4 + i] = u2[pp][i];
    }
    __syncthreads();

    if (g2_os == 0) {
        const u64* rp = (const u64*)(us + tid * 16);
#pragma unroll
        for (int pp = 0; pp < 2; ++pp)
#pragma unroll
            for (int i = 0; i < 4; ++i)
                u2[pp][i] = add2(u2[pp][i], rp[pp * 4 + i]);

        // unpack to per-pixel updates u[p][i]
        float u[4][4];
#pragma unroll
        for (int i = 0; i < 4; ++i) {
            unpack2(u2[0][i], u[0][i], u[1][i]);
            unpack2(u2[1][i], u[2][i], u[3][i]);
        }

        // ---------- epilogue: out = x + update * (rand_u > 0.5) ----------
        const int pbase = g2_pg * 4;
        const long rubase = ((long)b * 512 + row) * 512 + col0 + pbase;
        float4 r4 = *(const float4*)&ru[rubase];
        float m0 = r4.x > 0.5f ? 1.0f : 0.0f;
        float m1 = r4.y > 0.5f ? 1.0f : 0.0f;
        float m2 = r4.z > 0.5f ? 1.0f : 0.0f;
        float m3 = r4.w > 0.5f ? 1.0f : 0.0f;
#pragma unroll
        for (int ki = 0; ki < 4; ++ki) {
            int ko = g2_kog * 4 + ki;
            float4 xc = *(const float4*)&ys[ko * PITCH + pbase];
            float4 o4;
            o4.x = xc.x + u[0][ki] * m0;
            o4.y = xc.y + u[1][ki] * m1;
            o4.z = xc.z + u[2][ki] * m2;
            o4.w = xc.w + u[3][ki] * m3;
            long oidx = (((long)b * 16 + ko) * 512 + row) * 512 + col0 + pbase;
            *(float4*)&out[oidx] = o4;
        }
    }
}

extern "C" void kernel_launch(void* const* d_in, const int* in_sizes, int n_in,
                              void* d_out, int out_size) {
    const float* x  = (const float*)d_in[0];
    const float* w0 = (const float*)d_in[1];
    const float* b0 = (const float*)d_in[2];
    const float* w1 = (const float*)d_in[3];
    const float* ru = (const float*)d_in[4];
    float* out = (float*)d_out;

    cudaFuncSetAttribute(ca_kernel, cudaFuncAttributeMaxDynamicSharedMemorySize, SMEM_BYTES);
    dim3 grid(4, 512, 4);   // (col-block, row, batch)
    ca_kernel<<<grid, 256, SMEM_BYTES>>>(x, w0, b0, w1, ru, out);
}